// round 12
// baseline (speedup 1.0000x reference)
#include <cuda_runtime.h>
#include <cstdint>
#include <cstddef>

// ---------------------------------------------------------------------------
// 2-layer GraphSAGE mean-aggregator + segment sum + SELU readout.
//
// R12:
//  K1u: (R10-proven, unchanged) unified warp-specialized persistent kernel,
//       grid 148, 640 thr, 3-slot mbarrier ring; a12 tiles + a01 tiles.
//  K2r: k2b + readout merged. 125 CTAs (one wave), 320 thr:
//       - cp.async double-buffered K-halves (GEMM half0 overlaps W-half1 load)
//       - seg atomics, then CTAs<64 pre-stage readout weights,
//         epoch grid barrier, readout MLP from smem.
// ---------------------------------------------------------------------------

static constexpr int NN  = 10000;
static constexpr int DIM = 64;
static constexpr int G   = 64;

__device__ float g_ma12[NN * 128];
__device__ float g_a01 [NN * 128];
__device__ float g_seg [G * 128];
__device__ unsigned g_bar = 0;

// ---------------------------------------------------------------------------
__device__ __forceinline__ void fma2(unsigned long long& a,
                                     unsigned long long x, unsigned long long w) {
    asm("fma.rn.f32x2 %0, %1, %2, %3;" : "=l"(a) : "l"(x), "l"(w), "l"(a));
}
__device__ __forceinline__ void fadd2(unsigned long long& a, unsigned long long b) {
    asm("add.rn.f32x2 %0, %1, %2;" : "=l"(a) : "l"(a), "l"(b));
}
__device__ __forceinline__ unsigned long long fmul2(unsigned long long a,
                                                    unsigned long long b) {
    unsigned long long r;
    asm("mul.rn.f32x2 %0, %1, %2;" : "=l"(r) : "l"(a), "l"(b));
    return r;
}
__device__ __forceinline__ unsigned long long pack2(float x) {
    unsigned long long r;
    asm("mov.b64 %0, {%1, %1};" : "=l"(r) : "f"(x));
    return r;
}
__device__ __forceinline__ void unpack2(unsigned long long v, float& lo, float& hi) {
    asm("mov.b64 {%0, %1}, %2;" : "=f"(lo), "=f"(hi) : "l"(v));
}
__device__ __forceinline__ float selu_f(float x) {
    const float SC = 1.0507009873554805f;
    const float AL = 1.6732632423543772f;
    return SC * (x > 0.0f ? x : AL * (expf(x) - 1.0f));
}

// ---- mbarrier / smem helpers ----
__device__ __forceinline__ uint32_t smem_u32(const void* p) {
    uint32_t a;
    asm("{ .reg .u64 t; cvta.to.shared.u64 t, %1; cvt.u32.u64 %0, t; }"
        : "=r"(a) : "l"(p));
    return a;
}
__device__ __forceinline__ void mbar_init(uint32_t addr, uint32_t count) {
    asm volatile("mbarrier.init.shared.b64 [%0], %1;" :: "r"(addr), "r"(count)
                 : "memory");
}
__device__ __forceinline__ void mbar_arrive(uint32_t addr) {
    asm volatile("mbarrier.arrive.shared.b64 _, [%0];" :: "r"(addr) : "memory");
}
__device__ __forceinline__ void mbar_wait(uint32_t addr, uint32_t parity) {
    asm volatile(
        "{\n\t"
        ".reg .pred P1;\n\t"
        "WAIT_LOOP_%=:\n\t"
        "mbarrier.try_wait.parity.acquire.cta.shared::cta.b64 P1, [%0], %1, 0x989680;\n\t"
        "@P1 bra.uni WAIT_DONE_%=;\n\t"
        "bra.uni WAIT_LOOP_%=;\n\t"
        "WAIT_DONE_%=:\n\t"
        "}"
        :: "r"(addr), "r"(parity) : "memory");
}

// ---- cp.async helpers ----
__device__ __forceinline__ void cp_async16(uint32_t smem_addr, const void* gptr) {
    asm volatile("cp.async.cg.shared.global [%0], [%1], 16;"
                 :: "r"(smem_addr), "l"(gptr) : "memory");
}
__device__ __forceinline__ void cp_async_commit() {
    asm volatile("cp.async.commit_group;" ::: "memory");
}
template <int N>
__device__ __forceinline__ void cp_async_wait() {
    asm volatile("cp.async.wait_group %0;" :: "n"(N) : "memory");
}

// ---- epoch-based software grid barrier (all CTAs co-resident) ----
__device__ __forceinline__ void grid_barrier(unsigned* bar) {
    __threadfence();
    __syncthreads();
    if (threadIdx.x == 0) {
        unsigned ticket = atomicAdd(bar, 1u);
        unsigned target = (ticket / gridDim.x + 1u) * gridDim.x;
        unsigned v;
        do {
            asm volatile("ld.acquire.gpu.u32 %0, [%1];"
                         : "=r"(v) : "l"(bar) : "memory");
        } while (v < target);
    }
    __syncthreads();
}

// One k-group (4 k) of the R-row x 8-col GEMM (cols tx*4.., 64+tx*4..).
template <int KP, int R>
__device__ __forceinline__ void kgroupR(const float* __restrict__ Xp,
                                        const float* __restrict__ WA,
                                        const float* __restrict__ WB,
                                        int g, unsigned long long (&acc2)[R][4]) {
    float4 x4[R];
#pragma unroll
    for (int r = 0; r < R; r++) x4[r] = *(const float4*)(Xp + r * KP + g * 4);
#pragma unroll
    for (int kk = 0; kk < 4; kk++) {
        ulonglong2 wa = *(const ulonglong2*)(WA + (g * 4 + kk) * 128);
        ulonglong2 wb = *(const ulonglong2*)(WB + (g * 4 + kk) * 128);
#pragma unroll
        for (int r = 0; r < R; r++) {
            float xs = kk == 0 ? x4[r].x : kk == 1 ? x4[r].y
                     : kk == 2 ? x4[r].z : x4[r].w;
            unsigned long long xx = pack2(xs);
            fma2(acc2[r][0], xx, wa.x);
            fma2(acc2[r][1], xx, wa.y);
            fma2(acc2[r][2], xx, wb.x);
            fma2(acc2[r][3], xx, wb.y);
        }
    }
}

template <int K, int KP, int R>
__device__ __forceinline__ void gemm_core(const float* __restrict__ Xs,
                                          const float* __restrict__ Ws,
                                          int tx, int ty,
                                          unsigned long long (&acc2)[R][4]) {
    const float* Xp = Xs + ty * R * KP;
    const float* WA = Ws + tx * 4;
    const float* WB = Ws + 64 + tx * 4;
#pragma unroll 4
    for (int g = 0; g < K / 4; g++) kgroupR<KP, R>(Xp, WA, WB, g, acc2);
}

// ---------------------------------------------------------------------------
// K1u: unified persistent WS kernel (R10, unchanged). grid 148, 640 thr.
// smem: Xs[3] 80x132 (126720 B) + Ws 128x128 (65536 B) + 6 mbarriers (48 B).
// ---------------------------------------------------------------------------
static constexpr int K1_SLOT  = 80 * 132;
static constexpr int K1_BAROF = (3 * K1_SLOT + 128 * 128) * 4;
static constexpr int NT_A12   = 1250;
static constexpr int NT_A01   = 125;
static constexpr int NT_TOT   = NT_A12 + NT_A01;

__global__ void __launch_bounds__(640, 1)
k1u(const float* __restrict__ h0, const float* __restrict__ h1,
    const float* __restrict__ h2,
    const float* __restrict__ w0, const float* __restrict__ b0,
    float* __restrict__ ma12, float* __restrict__ a01) {
    extern __shared__ float smem[];
    float* Ws = smem + 3 * K1_SLOT;

    const int tid = threadIdx.x;
    const bool prod = (tid >= 320);
    const uint32_t sb = smem_u32(smem);
    const uint32_t barf = sb + K1_BAROF;
    const uint32_t bare = sb + K1_BAROF + 24;

    if (blockIdx.x == 0) {
        for (int i = tid; i < G * 128; i += 640) g_seg[i] = 0.0f;
    }
    if (tid == 0) {
#pragma unroll
        for (int s = 0; s < 3; s++) {
            mbar_init(barf + s * 8, 320);
            mbar_init(bare + s * 8, 320);
        }
    }

    const int ptid = prod ? (tid - 320) : 0;
    int r_s[4], c_s[4];
#pragma unroll
    for (int s = 0; s < 4; s++) {
        int idx = ptid + s * 320;
        r_s[s] = idx >> 4;
        c_s[s] = (idx & 15) << 2;
    }

    const int tx = tid & 15, ty = tid >> 4;
    float bv[8];
    if (!prod) {
#pragma unroll
        for (int it = 0; it < 13; it++) {
            int i = tid + it * 320;
            if (i < 4096)
                *(float4*)(Ws + i * 4) = *(const float4*)(w0 + i * 4);
        }
#pragma unroll
        for (int j = 0; j < 4; j++) {
            bv[j]     = b0[tx * 4 + j];
            bv[4 + j] = b0[64 + tx * 4 + j];
        }
    }
    __syncthreads();

    const int nt = (NT_TOT - blockIdx.x + gridDim.x - 1) / gridDim.x;

    if (prod) {
        const unsigned long long s04 = pack2(0.04f);
        const unsigned long long s10 = pack2(0.1f);
        int stage = 0, phase = 1;
        for (int i = 0; i < nt; i++) {
            const int t = blockIdx.x + i * gridDim.x;
            mbar_wait(bare + stage * 8, (uint32_t)phase);
            float* Xn = smem + stage * K1_SLOT;

            if (t < NT_A12) {
                const int rb = t * 80;
                const float* h2b = h2 + (size_t)rb * 1600;
                unsigned long long m2[4][2];
#pragma unroll
                for (int s = 0; s < 4; s++) { m2[s][0] = 0ULL; m2[s][1] = 0ULL; }
#pragma unroll 5
                for (int j = 0; j < 25; j++) {
#pragma unroll
                    for (int s = 0; s < 4; s++) {
                        ulonglong2 u = *(const ulonglong2*)(h2b
                            + (size_t)r_s[s] * 1600 + c_s[s] + j * 64);
                        fadd2(m2[s][0], u.x);
                        fadd2(m2[s][1], u.y);
                    }
                }
#pragma unroll
                for (int s = 0; s < 4; s++) {
                    *(ulonglong2*)(Xn + r_s[s] * 132 + 64 + c_s[s]) =
                        make_ulonglong2(fmul2(m2[s][0], s04), fmul2(m2[s][1], s04));
                    *(float4*)(Xn + r_s[s] * 132 + c_s[s]) =
                        *(const float4*)(h1 + (size_t)(rb + r_s[s]) * 64 + c_s[s]);
                }
            } else {
                const int rb = (t - NT_A12) * 80;
                unsigned long long m1[4][2];
#pragma unroll
                for (int s = 0; s < 4; s++) { m1[s][0] = 0ULL; m1[s][1] = 0ULL; }
#pragma unroll
                for (int j = 0; j < 10; j++) {
#pragma unroll
                    for (int s = 0; s < 4; s++) {
                        ulonglong2 u = *(const ulonglong2*)(h1
                            + ((size_t)(rb + r_s[s]) * 10 + j) * 64 + c_s[s]);
                        fadd2(m1[s][0], u.x);
                        fadd2(m1[s][1], u.y);
                    }
                }
#pragma unroll
                for (int s = 0; s < 4; s++) {
                    *(ulonglong2*)(Xn + r_s[s] * 132 + 64 + c_s[s]) =
                        make_ulonglong2(fmul2(m1[s][0], s10), fmul2(m1[s][1], s10));
                    *(float4*)(Xn + r_s[s] * 132 + c_s[s]) =
                        *(const float4*)(h0 + (size_t)(rb + r_s[s]) * 64 + c_s[s]);
                }
            }
            mbar_arrive(barf + stage * 8);
            if (++stage == 3) { stage = 0; phase ^= 1; }
        }
    } else {
        int stage = 0, phase = 0;
        for (int i = 0; i < nt; i++) {
            const int t = blockIdx.x + i * gridDim.x;
            mbar_wait(barf + stage * 8, (uint32_t)phase);
            float* Xc = smem + stage * K1_SLOT;

            unsigned long long acc2[4][4];
#pragma unroll
            for (int r = 0; r < 4; r++)
#pragma unroll
                for (int p = 0; p < 4; p++) acc2[r][p] = 0ULL;

            gemm_core<128, 132, 4>(Xc, Ws, tx, ty, acc2);

            if (t < NT_A12) {
#pragma unroll
                for (int r = 0; r < 4; r++) {
                    float v[8];
#pragma unroll
                    for (int p = 0; p < 4; p++)
                        unpack2(acc2[r][p], v[2 * p], v[2 * p + 1]);
#pragma unroll
                    for (int j = 0; j < 8; j++) {
                        float q = v[j] + bv[j];
                        v[j] = q > 0.0f ? q : 0.0f;
                    }
                    float* dr = Xc + (ty * 4 + r) * 132;
                    *(float4*)(dr + tx * 4)      = make_float4(v[0], v[1], v[2], v[3]);
                    *(float4*)(dr + 64 + tx * 4) = make_float4(v[4], v[5], v[6], v[7]);
                }
                asm volatile("bar.sync 1, 320;" ::: "memory");

#pragma unroll
                for (int it = 0; it < 4; it++) {
                    int o = tid + it * 320;
                    if (o < 1024) {
                        int gl = o >> 7, c = o & 127;
                        float s = 0.0f;
#pragma unroll
                        for (int r2 = 0; r2 < 10; r2++)
                            s += Xc[(gl * 10 + r2) * 132 + c];
                        ma12[(size_t)(t * 8 + gl) * 128 + c] = s * 0.1f;
                    }
                }
                mbar_arrive(bare + stage * 8);
            } else {
                mbar_arrive(bare + stage * 8);
                const int rb = (t - NT_A12) * 80;
#pragma unroll
                for (int r = 0; r < 4; r++) {
                    float v[8];
#pragma unroll
                    for (int p = 0; p < 4; p++)
                        unpack2(acc2[r][p], v[2 * p], v[2 * p + 1]);
#pragma unroll
                    for (int j = 0; j < 8; j++) {
                        float q = v[j] + bv[j];
                        v[j] = q > 0.0f ? q : 0.0f;
                    }
                    float* dr = a01 + (size_t)(rb + ty * 4 + r) * 128;
                    *(float4*)(dr + tx * 4)      = make_float4(v[0], v[1], v[2], v[3]);
                    *(float4*)(dr + 64 + tx * 4) = make_float4(v[4], v[5], v[6], v[7]);
                }
            }
            if (++stage == 3) { stage = 0; phase ^= 1; }
        }
    }
}

// ---------------------------------------------------------------------------
// K2r: k2b (cp.async double-buffered K-halves) + grid barrier + readout.
// grid 125 (one wave), 320 thr, R=4.
// smem floats: Xs 80x260 (20800) | W0 16384 | W1 16384  = 214272 B.
// ---------------------------------------------------------------------------
static constexpr int K2_XS = 80 * 260;     // 20800 floats
static constexpr int K2_W0 = K2_XS;        // offset of W half 0
static constexpr int K2_W1 = K2_XS + 16384;

__global__ void __launch_bounds__(320)
k2r(const float* __restrict__ a01, const float* __restrict__ ma12,
    const float* __restrict__ w1, const float* __restrict__ b1,
    const float* __restrict__ wr1, const float* __restrict__ br1,
    const float* __restrict__ wr2, const float* __restrict__ br2,
    const float* __restrict__ wr3, const float* __restrict__ br3,
    const int* __restrict__ gid, float* __restrict__ outp, int n) {
    extern __shared__ float smem[];
    float* Xs = smem;
    float* W0 = smem + K2_W0;
    float* W1 = smem + K2_W1;
    const uint32_t sb = smem_u32(smem);

    const int tid = threadIdx.x;
    const int rb  = blockIdx.x * 80;

    // group A: X tile + W half 0 via cp.async
#pragma unroll
    for (int it = 0; it < 16; it++) {
        int i = tid + it * 320;
        int r = i >> 6, c = (i & 63) << 2;
        int row = rb + r;
        const float* src = (c < 128)
            ? (a01  + (size_t)row * 128 + c)
            : (ma12 + (size_t)row * 128 + c - 128);
        cp_async16(sb + (uint32_t)(r * 260 + c) * 4, src);
    }
#pragma unroll
    for (int it = 0; it < 13; it++) {
        int i = tid + it * 320;
        if (i < 4096)
            cp_async16(sb + (uint32_t)(K2_W0 + i * 4) * 4, w1 + i * 4);
    }
    cp_async_commit();
    // group B: W half 1
#pragma unroll
    for (int it = 0; it < 13; it++) {
        int i = tid + it * 320;
        if (i < 4096)
            cp_async16(sb + (uint32_t)(K2_W1 + i * 4) * 4, w1 + 16384 + i * 4);
    }
    cp_async_commit();

    cp_async_wait<1>();   // group A landed; group B still in flight
    __syncthreads();

    const int tx = tid & 15, ty = tid >> 4;   // ty 0..19, R=4
    unsigned long long acc2[4][4];
#pragma unroll
    for (int r = 0; r < 4; r++)
#pragma unroll
        for (int p = 0; p < 4; p++) acc2[r][p] = 0ULL;

    gemm_core<128, 260, 4>(Xs, W0, tx, ty, acc2);   // K half 0

    cp_async_wait<0>();   // group B landed
    __syncthreads();

    gemm_core<128, 260, 4>(Xs + 128, W1, tx, ty, acc2);   // K half 1

    float bv[8];
#pragma unroll
    for (int j = 0; j < 4; j++) {
        bv[j]     = b1[tx * 4 + j];
        bv[4 + j] = b1[64 + tx * 4 + j];
    }
#pragma unroll
    for (int r = 0; r < 4; r++) {
        int row = rb + ty * 4 + r;
        if (row >= n) continue;
        float v[8];
#pragma unroll
        for (int p = 0; p < 4; p++) unpack2(acc2[r][p], v[2 * p], v[2 * p + 1]);
        int g = gid[row];
        float* sp = g_seg + (size_t)g * 128;
#pragma unroll
        for (int j = 0; j < 4; j++) {
            float q = v[j] + bv[j];
            atomicAdd(sp + tx * 4 + j, q > 0.0f ? q : 0.0f);
        }
#pragma unroll
        for (int j = 0; j < 4; j++) {
            float q = v[4 + j] + bv[4 + j];
            atomicAdd(sp + 64 + tx * 4 + j, q > 0.0f ? q : 0.0f);
        }
    }

    // ---- readout prep: CTAs < 64 stage weights into smem BEFORE barrier ----
    __syncthreads();   // all GEMM reads of Xs done; safe to overwrite
    float* w1s  = Xs;           // 4480
    float* w2s  = Xs + 4480;    // 1225
    float* b1s  = Xs + 5705;    // 35
    float* b2s  = Xs + 5740;    // 35
    float* w3s  = Xs + 5775;    // 35
    float* segs = Xs + 5810;    // 128
    float* r1s  = Xs + 5938;    // 35
    float* r2s  = Xs + 5973;    // 35

    if (blockIdx.x < G) {
#pragma unroll
        for (int it = 0; it < 4; it++) {
            int i = tid + it * 320;
            if (i < 1120)
                *(float4*)(w1s + i * 4) = *(const float4*)(wr1 + i * 4);
        }
#pragma unroll
        for (int it = 0; it < 4; it++) {
            int i = tid + it * 320;
            if (i < 1225) w2s[i] = wr2[i];
        }
        if (tid < 35) { b1s[tid] = br1[tid]; b2s[tid] = br2[tid]; w3s[tid] = wr3[tid]; }
    }

    grid_barrier(&g_bar);   // all seg atomics complete

    if (blockIdx.x < G) {
        const int g = blockIdx.x;
        if (tid < 128) segs[tid] = g_seg[g * 128 + tid];
        __syncthreads();

        if (tid < 35) {
            float a0 = 0.f, a1 = 0.f, a2 = 0.f, a3 = 0.f;
#pragma unroll 8
            for (int k = 0; k < 128; k += 4) {
                a0 = fmaf(segs[k],     w1s[(k)     * 35 + tid], a0);
                a1 = fmaf(segs[k + 1], w1s[(k + 1) * 35 + tid], a1);
                a2 = fmaf(segs[k + 2], w1s[(k + 2) * 35 + tid], a2);
                a3 = fmaf(segs[k + 3], w1s[(k + 3) * 35 + tid], a3);
            }
            r1s[tid] = selu_f((a0 + a1) + (a2 + a3) + b1s[tid]);
        }
        __syncthreads();

        if (tid < 35) {
            float a0 = 0.f, a1 = 0.f;
#pragma unroll
            for (int k = 0; k < 34; k += 2) {
                a0 = fmaf(r1s[k],     w2s[(k)     * 35 + tid], a0);
                a1 = fmaf(r1s[k + 1], w2s[(k + 1) * 35 + tid], a1);
            }
            a0 = fmaf(r1s[34], w2s[34 * 35 + tid], a0);
            r2s[tid] = selu_f(a0 + a1 + b2s[tid]) * w3s[tid];
        }
        __syncthreads();

        if (tid == 0) {
            float acc = br3[0];
#pragma unroll
            for (int j = 0; j < 35; j++) acc += r2s[j];
            outp[g] = acc;
        }
    }
}

// ---------------------------------------------------------------------------
extern "C" void kernel_launch(void* const* d_in, const int* in_sizes, int n_in,
                              void* d_out, int out_size) {
    const float* h0  = (const float*)d_in[0];
    const float* h1  = (const float*)d_in[1];
    const float* h2  = (const float*)d_in[2];
    const float* w0  = (const float*)d_in[3];
    const float* b0  = (const float*)d_in[4];
    const float* w1  = (const float*)d_in[5];
    const float* b1  = (const float*)d_in[6];
    const float* wr1 = (const float*)d_in[7];
    const float* br1 = (const float*)d_in[8];
    const float* wr2 = (const float*)d_in[9];
    const float* br2 = (const float*)d_in[10];
    const float* wr3 = (const float*)d_in[11];
    const float* br3 = (const float*)d_in[12];
    const int*   gid = (const int*)d_in[13];

    const int n = in_sizes[0] / DIM;    // 10000

    float *ma12, *a01;
    cudaGetSymbolAddress((void**)&ma12, g_ma12);
    cudaGetSymbolAddress((void**)&a01,  g_a01);

    constexpr int SMEM_K1 = K1_BAROF + 48;                 // 192304
    constexpr int SMEM_K2 = (K2_XS + 2 * 16384) * 4;       // 214272
    cudaFuncSetAttribute((const void*)k1u,
                         cudaFuncAttributeMaxDynamicSharedMemorySize, SMEM_K1);
    cudaFuncSetAttribute((const void*)k2r,
                         cudaFuncAttributeMaxDynamicSharedMemorySize, SMEM_K2);

    // K1u: a12 + a01 tiles in one persistent launch; zeroes seg.
    k1u<<<148, 640, SMEM_K1>>>(h0, h1, h2, w0, b0, ma12, a01);

    // K2r: round-1 GEMM + segment-sum + grid barrier + readout.
    k2r<<<125, 320, SMEM_K2>>>(a01, ma12, w1, b1,
                               wr1, br1, wr2, br2, wr3, br3,
                               gid, (float*)d_out, n);
}

// round 13
// speedup vs baseline: 1.0742x; 1.0742x over previous
#include <cuda_runtime.h>
#include <cstdint>
#include <cstddef>

// ---------------------------------------------------------------------------
// 2-layer GraphSAGE mean-aggregator + segment sum + SELU readout.
//
// R13 = R10 (proven 166.6us) + two k1u-only deltas:
//   (1) cooperative prologue: ALL 640 threads fill ring slot 0, producers
//       then arrive on full[0]; consumer loop identical to R10.
//   (2) k1u grid = device SM count (152 on GB300).
// k2b and readout are byte-for-byte R10.
// ---------------------------------------------------------------------------

static constexpr int NN  = 10000;
static constexpr int DIM = 64;
static constexpr int G   = 64;

__device__ float g_ma12[NN * 128];
__device__ float g_a01 [NN * 128];
__device__ float g_seg [G * 128];

// ---------------------------------------------------------------------------
__device__ __forceinline__ void fma2(unsigned long long& a,
                                     unsigned long long x, unsigned long long w) {
    asm("fma.rn.f32x2 %0, %1, %2, %3;" : "=l"(a) : "l"(x), "l"(w), "l"(a));
}
__device__ __forceinline__ void fadd2(unsigned long long& a, unsigned long long b) {
    asm("add.rn.f32x2 %0, %1, %2;" : "=l"(a) : "l"(a), "l"(b));
}
__device__ __forceinline__ unsigned long long fmul2(unsigned long long a,
                                                    unsigned long long b) {
    unsigned long long r;
    asm("mul.rn.f32x2 %0, %1, %2;" : "=l"(r) : "l"(a), "l"(b));
    return r;
}
__device__ __forceinline__ unsigned long long pack2(float x) {
    unsigned long long r;
    asm("mov.b64 %0, {%1, %1};" : "=l"(r) : "f"(x));
    return r;
}
__device__ __forceinline__ void unpack2(unsigned long long v, float& lo, float& hi) {
    asm("mov.b64 {%0, %1}, %2;" : "=f"(lo), "=f"(hi) : "l"(v));
}
__device__ __forceinline__ float selu_f(float x) {
    const float SC = 1.0507009873554805f;
    const float AL = 1.6732632423543772f;
    return SC * (x > 0.0f ? x : AL * (expf(x) - 1.0f));
}

// ---- mbarrier helpers ----
__device__ __forceinline__ uint32_t smem_u32(const void* p) {
    uint32_t a;
    asm("{ .reg .u64 t; cvta.to.shared.u64 t, %1; cvt.u32.u64 %0, t; }"
        : "=r"(a) : "l"(p));
    return a;
}
__device__ __forceinline__ void mbar_init(uint32_t addr, uint32_t count) {
    asm volatile("mbarrier.init.shared.b64 [%0], %1;" :: "r"(addr), "r"(count)
                 : "memory");
}
__device__ __forceinline__ void mbar_arrive(uint32_t addr) {
    asm volatile("mbarrier.arrive.shared.b64 _, [%0];" :: "r"(addr) : "memory");
}
__device__ __forceinline__ void mbar_wait(uint32_t addr, uint32_t parity) {
    asm volatile(
        "{\n\t"
        ".reg .pred P1;\n\t"
        "WAIT_LOOP_%=:\n\t"
        "mbarrier.try_wait.parity.acquire.cta.shared::cta.b64 P1, [%0], %1, 0x989680;\n\t"
        "@P1 bra.uni WAIT_DONE_%=;\n\t"
        "bra.uni WAIT_LOOP_%=;\n\t"
        "WAIT_DONE_%=:\n\t"
        "}"
        :: "r"(addr), "r"(parity) : "memory");
}

// One k-group (4 k) of the R-row x 8-col GEMM (cols tx*4.., 64+tx*4..).
template <int KP, int R>
__device__ __forceinline__ void kgroupR(const float* __restrict__ Xp,
                                        const float* __restrict__ WA,
                                        const float* __restrict__ WB,
                                        int g, unsigned long long (&acc2)[R][4]) {
    float4 x4[R];
#pragma unroll
    for (int r = 0; r < R; r++) x4[r] = *(const float4*)(Xp + r * KP + g * 4);
#pragma unroll
    for (int kk = 0; kk < 4; kk++) {
        ulonglong2 wa = *(const ulonglong2*)(WA + (g * 4 + kk) * 128);
        ulonglong2 wb = *(const ulonglong2*)(WB + (g * 4 + kk) * 128);
#pragma unroll
        for (int r = 0; r < R; r++) {
            float xs = kk == 0 ? x4[r].x : kk == 1 ? x4[r].y
                     : kk == 2 ? x4[r].z : x4[r].w;
            unsigned long long xx = pack2(xs);
            fma2(acc2[r][0], xx, wa.x);
            fma2(acc2[r][1], xx, wa.y);
            fma2(acc2[r][2], xx, wb.x);
            fma2(acc2[r][3], xx, wb.y);
        }
    }
}

template <int K, int KP, int R>
__device__ __forceinline__ void gemm_core(const float* __restrict__ Xs,
                                          const float* __restrict__ Ws,
                                          int tx, int ty,
                                          unsigned long long (&acc2)[R][4]) {
    const float* Xp = Xs + ty * R * KP;
    const float* WA = Ws + tx * 4;
    const float* WB = Ws + 64 + tx * 4;
#pragma unroll 4
    for (int g = 0; g < K / 4; g++) kgroupR<KP, R>(Xp, WA, WB, g, acc2);
}

// ---------------------------------------------------------------------------
// K1u: unified persistent WS kernel. grid = SM count, 640 thr, 1 CTA/SM.
// smem: Xs[3] 80x132 (126720 B) + Ws 128x128 (65536 B) + 6 mbarriers (48 B).
// ---------------------------------------------------------------------------
static constexpr int K1_SLOT  = 80 * 132;
static constexpr int K1_BAROF = (3 * K1_SLOT + 128 * 128) * 4;
static constexpr int NT_A12   = 1250;
static constexpr int NT_A01   = 125;
static constexpr int NT_TOT   = NT_A12 + NT_A01;

__global__ void __launch_bounds__(640, 1)
k1u(const float* __restrict__ h0, const float* __restrict__ h1,
    const float* __restrict__ h2,
    const float* __restrict__ w0, const float* __restrict__ b0,
    float* __restrict__ ma12, float* __restrict__ a01) {
    extern __shared__ float smem[];
    float* Ws = smem + 3 * K1_SLOT;

    const int tid = threadIdx.x;
    const bool prod = (tid >= 320);
    const uint32_t sb = smem_u32(smem);
    const uint32_t barf = sb + K1_BAROF;
    const uint32_t bare = sb + K1_BAROF + 24;

    if (blockIdx.x == 0) {
        for (int i = tid; i < G * 128; i += 640) g_seg[i] = 0.0f;
    }
    if (tid == 0) {
#pragma unroll
        for (int s = 0; s < 3; s++) {
            mbar_init(barf + s * 8, 320);
            mbar_init(bare + s * 8, 320);
        }
    }

    // producer slot geometry (4 slots, stride 320)
    const int ptid = prod ? (tid - 320) : 0;
    int r_s[4], c_s[4];
#pragma unroll
    for (int s = 0; s < 4; s++) {
        int idx = ptid + s * 320;
        r_s[s] = idx >> 4;
        c_s[s] = (idx & 15) << 2;
    }

    const int tx = tid & 15, ty = tid >> 4;
    float bv[8];
    if (!prod) {
#pragma unroll
        for (int it = 0; it < 13; it++) {
            int i = tid + it * 320;
            if (i < 4096)
                *(float4*)(Ws + i * 4) = *(const float4*)(w0 + i * 4);
        }
#pragma unroll
        for (int j = 0; j < 4; j++) {
            bv[j]     = b0[tx * 4 + j];
            bv[4 + j] = b0[64 + tx * 4 + j];
        }
    }
    __syncthreads();   // mbarrier init + Ws visible

    const int nt = (NT_TOT - blockIdx.x + gridDim.x - 1) / gridDim.x;

    // ---- cooperative prologue: ALL 640 threads fill slot 0 with tile t0 ----
    // (t0 = blockIdx.x < 1250, so always an a12 tile: h1 + mean25(h2))
    {
        const int rb = blockIdx.x * 80;
        const float* h2b = h2 + (size_t)rb * 1600;
        float* X0 = smem;
        const unsigned long long s04 = pack2(0.04f);
#pragma unroll
        for (int s = 0; s < 2; s++) {
            int idx = tid + s * 640;
            int rr = idx >> 4, cc = (idx & 15) << 2;
            unsigned long long m0 = 0ULL, m1v = 0ULL;
#pragma unroll 5
            for (int j = 0; j < 25; j++) {
                ulonglong2 u = *(const ulonglong2*)(h2b
                    + (size_t)rr * 1600 + cc + j * 64);
                fadd2(m0, u.x);
                fadd2(m1v, u.y);
            }
            *(ulonglong2*)(X0 + rr * 132 + 64 + cc) =
                make_ulonglong2(fmul2(m0, s04), fmul2(m1v, s04));
            *(float4*)(X0 + rr * 132 + cc) =
                *(const float4*)(h1 + (size_t)(rb + rr) * 64 + cc);
        }
    }
    __syncthreads();   // slot 0 complete, visible to all

    if (prod) {
        // signal full[0] for the pre-filled tile (320 arrivals)
        mbar_arrive(barf);

        const unsigned long long s04 = pack2(0.04f);
        const unsigned long long s10 = pack2(0.1f);
        int stage = 1, phase = 1;   // slot 0 already produced
        for (int i = 1; i < nt; i++) {
            const int t = blockIdx.x + i * gridDim.x;
            mbar_wait(bare + stage * 8, (uint32_t)phase);
            float* Xn = smem + stage * K1_SLOT;

            if (t < NT_A12) {
                const int rb = t * 80;
                const float* h2b = h2 + (size_t)rb * 1600;
                unsigned long long m2[4][2];
#pragma unroll
                for (int s = 0; s < 4; s++) { m2[s][0] = 0ULL; m2[s][1] = 0ULL; }
#pragma unroll 5
                for (int j = 0; j < 25; j++) {
#pragma unroll
                    for (int s = 0; s < 4; s++) {
                        ulonglong2 u = *(const ulonglong2*)(h2b
                            + (size_t)r_s[s] * 1600 + c_s[s] + j * 64);
                        fadd2(m2[s][0], u.x);
                        fadd2(m2[s][1], u.y);
                    }
                }
#pragma unroll
                for (int s = 0; s < 4; s++) {
                    *(ulonglong2*)(Xn + r_s[s] * 132 + 64 + c_s[s]) =
                        make_ulonglong2(fmul2(m2[s][0], s04), fmul2(m2[s][1], s04));
                    *(float4*)(Xn + r_s[s] * 132 + c_s[s]) =
                        *(const float4*)(h1 + (size_t)(rb + r_s[s]) * 64 + c_s[s]);
                }
            } else {
                const int rb = (t - NT_A12) * 80;
                unsigned long long m1[4][2];
#pragma unroll
                for (int s = 0; s < 4; s++) { m1[s][0] = 0ULL; m1[s][1] = 0ULL; }
#pragma unroll
                for (int j = 0; j < 10; j++) {
#pragma unroll
                    for (int s = 0; s < 4; s++) {
                        ulonglong2 u = *(const ulonglong2*)(h1
                            + ((size_t)(rb + r_s[s]) * 10 + j) * 64 + c_s[s]);
                        fadd2(m1[s][0], u.x);
                        fadd2(m1[s][1], u.y);
                    }
                }
#pragma unroll
                for (int s = 0; s < 4; s++) {
                    *(ulonglong2*)(Xn + r_s[s] * 132 + 64 + c_s[s]) =
                        make_ulonglong2(fmul2(m1[s][0], s10), fmul2(m1[s][1], s10));
                    *(float4*)(Xn + r_s[s] * 132 + c_s[s]) =
                        *(const float4*)(h0 + (size_t)(rb + r_s[s]) * 64 + c_s[s]);
                }
            }
            mbar_arrive(barf + stage * 8);
            if (++stage == 3) { stage = 0; phase ^= 1; }
        }
    } else {
        // consumer loop: identical to R10
        int stage = 0, phase = 0;
        for (int i = 0; i < nt; i++) {
            const int t = blockIdx.x + i * gridDim.x;
            mbar_wait(barf + stage * 8, (uint32_t)phase);
            float* Xc = smem + stage * K1_SLOT;

            unsigned long long acc2[4][4];
#pragma unroll
            for (int r = 0; r < 4; r++)
#pragma unroll
                for (int p = 0; p < 4; p++) acc2[r][p] = 0ULL;

            gemm_core<128, 132, 4>(Xc, Ws, tx, ty, acc2);

            if (t < NT_A12) {
#pragma unroll
                for (int r = 0; r < 4; r++) {
                    float v[8];
#pragma unroll
                    for (int p = 0; p < 4; p++)
                        unpack2(acc2[r][p], v[2 * p], v[2 * p + 1]);
#pragma unroll
                    for (int j = 0; j < 8; j++) {
                        float q = v[j] + bv[j];
                        v[j] = q > 0.0f ? q : 0.0f;
                    }
                    float* dr = Xc + (ty * 4 + r) * 132;
                    *(float4*)(dr + tx * 4)      = make_float4(v[0], v[1], v[2], v[3]);
                    *(float4*)(dr + 64 + tx * 4) = make_float4(v[4], v[5], v[6], v[7]);
                }
                asm volatile("bar.sync 1, 320;" ::: "memory");

#pragma unroll
                for (int it = 0; it < 4; it++) {
                    int o = tid + it * 320;
                    if (o < 1024) {
                        int gl = o >> 7, c = o & 127;
                        float s = 0.0f;
#pragma unroll
                        for (int r2 = 0; r2 < 10; r2++)
                            s += Xc[(gl * 10 + r2) * 132 + c];
                        ma12[(size_t)(t * 8 + gl) * 128 + c] = s * 0.1f;
                    }
                }
                mbar_arrive(bare + stage * 8);
            } else {
                mbar_arrive(bare + stage * 8);
                const int rb = (t - NT_A12) * 80;
#pragma unroll
                for (int r = 0; r < 4; r++) {
                    float v[8];
#pragma unroll
                    for (int p = 0; p < 4; p++)
                        unpack2(acc2[r][p], v[2 * p], v[2 * p + 1]);
#pragma unroll
                    for (int j = 0; j < 8; j++) {
                        float q = v[j] + bv[j];
                        v[j] = q > 0.0f ? q : 0.0f;
                    }
                    float* dr = a01 + (size_t)(rb + ty * 4 + r) * 128;
                    *(float4*)(dr + tx * 4)      = make_float4(v[0], v[1], v[2], v[3]);
                    *(float4*)(dr + 64 + tx * 4) = make_float4(v[4], v[5], v[6], v[7]);
                }
            }
            if (++stage == 3) { stage = 0; phase ^= 1; }
        }
    }
}

// ---------------------------------------------------------------------------
// K2b (R10, unchanged): seg[g] += relu([a01 | ma12] @ w1 + b1).
// K=256, 80 rows, 320 thr (R=4), grid 125. smem 214272 B.
// ---------------------------------------------------------------------------
__global__ void __launch_bounds__(320)
k2b_fused(const float* __restrict__ a01, const float* __restrict__ ma12,
          const float* __restrict__ w1, const float* __restrict__ b1,
          const int* __restrict__ gid, float* __restrict__ seg, int n) {
    extern __shared__ float smem[];
    float* Xs = smem;               // 80 * 260
    float* Ws = smem + 80 * 260;    // 256 * 128

    const int tid = threadIdx.x;
    const int rb  = blockIdx.x * 80;

#pragma unroll
    for (int it = 0; it < 16; it++) {
        int i = tid + it * 320;
        int r = i >> 6, c = (i & 63) << 2;
        int row = rb + r;
        float4 v;
        if (c < 128) v = *(const float4*)(a01  + (size_t)row * 128 + c);
        else         v = *(const float4*)(ma12 + (size_t)row * 128 + c - 128);
        *(float4*)(Xs + r * 260 + c) = v;
    }
#pragma unroll
    for (int it = 0; it < 26; it++) {
        int i = tid + it * 320;
        if (i < 8192)
            *(float4*)(Ws + i * 4) = *(const float4*)(w1 + i * 4);
    }
    __syncthreads();

    const int tx = tid & 15, ty = tid >> 4;   // ty 0..19, R=4
    unsigned long long acc2[4][4];
#pragma unroll
    for (int r = 0; r < 4; r++)
#pragma unroll
        for (int p = 0; p < 4; p++) acc2[r][p] = 0ULL;
    gemm_core<256, 260, 4>(Xs, Ws, tx, ty, acc2);

    float bv[8];
#pragma unroll
    for (int j = 0; j < 4; j++) {
        bv[j]     = b1[tx * 4 + j];
        bv[4 + j] = b1[64 + tx * 4 + j];
    }
#pragma unroll
    for (int r = 0; r < 4; r++) {
        int row = rb + ty * 4 + r;
        if (row >= n) continue;
        float v[8];
#pragma unroll
        for (int p = 0; p < 4; p++) unpack2(acc2[r][p], v[2 * p], v[2 * p + 1]);
        int g = gid[row];
        float* sp = seg + (size_t)g * 128;
#pragma unroll
        for (int j = 0; j < 4; j++) {
            float q = v[j] + bv[j];
            atomicAdd(sp + tx * 4 + j, q > 0.0f ? q : 0.0f);
        }
#pragma unroll
        for (int j = 0; j < 4; j++) {
            float q = v[4 + j] + bv[4 + j];
            atomicAdd(sp + 64 + tx * 4 + j, q > 0.0f ? q : 0.0f);
        }
    }
}

// ---------------------------------------------------------------------------
// Readout MLP (R10, unchanged): one block per graph, 256 threads.
// ---------------------------------------------------------------------------
__global__ void __launch_bounds__(256)
readout_kernel(const float* __restrict__ seg,
               const float* __restrict__ wr1, const float* __restrict__ br1,
               const float* __restrict__ wr2, const float* __restrict__ br2,
               const float* __restrict__ wr3, const float* __restrict__ br3,
               float* __restrict__ outp) {
    __shared__ float w1s[128 * 35];
    __shared__ float w2s[35 * 35];
    __shared__ float b1s[35], b2s[35], w3s[35];
    __shared__ float segs[128];
    __shared__ float r1s[35];
    __shared__ float r2s[35];

    const int tid = threadIdx.x;
    const int g   = blockIdx.x;

#pragma unroll
    for (int it = 0; it < 5; it++) {
        int i = tid + it * 256;
        if (i < 1120)
            *(float4*)(w1s + i * 4) = *(const float4*)(wr1 + i * 4);
    }
#pragma unroll
    for (int it = 0; it < 5; it++) {
        int i = tid + it * 256;
        if (i < 1225) w2s[i] = wr2[i];
    }
    if (tid < 35) { b1s[tid] = br1[tid]; b2s[tid] = br2[tid]; w3s[tid] = wr3[tid]; }
    if (tid < 128) segs[tid] = seg[g * 128 + tid];
    __syncthreads();

    if (tid < 35) {
        float a0 = 0.f, a1 = 0.f, a2 = 0.f, a3 = 0.f;
#pragma unroll 8
        for (int k = 0; k < 128; k += 4) {
            a0 = fmaf(segs[k],     w1s[(k)     * 35 + tid], a0);
            a1 = fmaf(segs[k + 1], w1s[(k + 1) * 35 + tid], a1);
            a2 = fmaf(segs[k + 2], w1s[(k + 2) * 35 + tid], a2);
            a3 = fmaf(segs[k + 3], w1s[(k + 3) * 35 + tid], a3);
        }
        r1s[tid] = selu_f((a0 + a1) + (a2 + a3) + b1s[tid]);
    }
    __syncthreads();

    if (tid < 35) {
        float a0 = 0.f, a1 = 0.f;
#pragma unroll
        for (int k = 0; k < 34; k += 2) {
            a0 = fmaf(r1s[k],     w2s[(k)     * 35 + tid], a0);
            a1 = fmaf(r1s[k + 1], w2s[(k + 1) * 35 + tid], a1);
        }
        a0 = fmaf(r1s[34], w2s[34 * 35 + tid], a0);
        r2s[tid] = selu_f(a0 + a1 + b2s[tid]) * w3s[tid];
    }
    __syncthreads();

    if (tid == 0) {
        float acc = br3[0];
#pragma unroll
        for (int j = 0; j < 35; j++) acc += r2s[j];
        outp[g] = acc;
    }
}

// ---------------------------------------------------------------------------
extern "C" void kernel_launch(void* const* d_in, const int* in_sizes, int n_in,
                              void* d_out, int out_size) {
    const float* h0  = (const float*)d_in[0];
    const float* h1  = (const float*)d_in[1];
    const float* h2  = (const float*)d_in[2];
    const float* w0  = (const float*)d_in[3];
    const float* b0  = (const float*)d_in[4];
    const float* w1  = (const float*)d_in[5];
    const float* b1  = (const float*)d_in[6];
    const float* wr1 = (const float*)d_in[7];
    const float* br1 = (const float*)d_in[8];
    const float* wr2 = (const float*)d_in[9];
    const float* br2 = (const float*)d_in[10];
    const float* wr3 = (const float*)d_in[11];
    const float* br3 = (const float*)d_in[12];
    const int*   gid = (const int*)d_in[13];

    const int n = in_sizes[0] / DIM;    // 10000

    float *ma12, *a01, *seg;
    cudaGetSymbolAddress((void**)&ma12, g_ma12);
    cudaGetSymbolAddress((void**)&a01,  g_a01);
    cudaGetSymbolAddress((void**)&seg,  g_seg);

    int dev = 0, nsm = 148;
    cudaGetDevice(&dev);
    cudaDeviceGetAttribute(&nsm, cudaDevAttrMultiProcessorCount, dev);
    if (nsm < 64) nsm = 148;            // sanity fallback

    constexpr int SMEM_K1  = K1_BAROF + 48;                 // 192304
    constexpr int SMEM_K2B = (80 * 260 + 256 * 128) * 4;    // 214272
    cudaFuncSetAttribute((const void*)k1u,
                         cudaFuncAttributeMaxDynamicSharedMemorySize, SMEM_K1);
    cudaFuncSetAttribute((const void*)k2b_fused,
                         cudaFuncAttributeMaxDynamicSharedMemorySize, SMEM_K2B);

    // K1u: a12 + a01 tiles in one persistent launch (all SMs); zeroes seg.
    k1u<<<nsm, 640, SMEM_K1>>>(h0, h1, h2, w0, b0, ma12, a01);

    // K2b: round-1 GEMM + fused segment-sum (R10-proven shape).
    k2b_fused<<<125, 320, SMEM_K2B>>>(a01, ma12, w1, b1, gid, seg, n);

    // K3: readout (R10-proven).
    readout_kernel<<<G, 256>>>(seg, wr1, br1, wr2, br2, wr3, br3, (float*)d_out);
}